// round 10
// baseline (speedup 1.0000x reference)
#include <cuda_runtime.h>
#include <math.h>
#include <stdint.h>

// Problem constants
constexpr int kN  = 32768;
constexpr int kC  = 512;
constexpr int kC3 = 1536;
constexpr int kH  = 8;
constexpr int kD  = 64;
constexpr int kW  = 256;
constexpr int kNW = kN / kW;   // 128 windows
constexpr int kSHIFT = 128;
constexpr float kSCALE = 0.125f;  // 1/sqrt(64)

// Scratch (static device arrays — no allocation at runtime)
__device__ float g_qkv[(size_t)kN * kC3];  // 192 MB
__device__ float g_h[(size_t)kN * kC];     // attention output, un-rolled frame

__device__ __forceinline__ uint32_t f2tf32(float x) {
    uint32_t r;
    asm("cvt.rna.tf32.f32 %0, %1;" : "=r"(r) : "f"(x));
    return r;
}

__device__ __forceinline__ void mma_tf32(
    float& c0, float& c1, float& c2, float& c3,
    uint32_t a0, uint32_t a1, uint32_t a2, uint32_t a3,
    uint32_t b0, uint32_t b1)
{
    asm volatile(
        "mma.sync.aligned.m16n8k8.row.col.f32.tf32.tf32.f32 "
        "{%0,%1,%2,%3}, {%4,%5,%6,%7}, {%8,%9}, {%0,%1,%2,%3};"
        : "+f"(c0), "+f"(c1), "+f"(c2), "+f"(c3)
        : "r"(a0), "r"(a1), "r"(a2), "r"(a3), "r"(b0), "r"(b1));
}

// ---------------------------------------------------------------------------
// tf32 tensor-core GEMM with bias: C[M,Nn] = A[M,K] @ B[K,Nn] + bias[Nn]
// (unchanged — validated)
// ---------------------------------------------------------------------------
__global__ void __launch_bounds__(256, 2) gemm_tf32_bias(
    const float* __restrict__ A, const float* __restrict__ B,
    const float* __restrict__ bias, float* __restrict__ C,
    int M, int Nn, int K)
{
    constexpr int BM = 128, BN = 128, BK = 16;
    constexpr int ASTR = BK + 4;
    constexpr int BSTR = BN + 8;

    __shared__ float As[2][BM * ASTR];
    __shared__ float Bs[2][BK * BSTR];

    const int tid  = threadIdx.x;
    const int m0   = blockIdx.y * BM;
    const int n0   = blockIdx.x * BN;
    const int lane = tid & 31;
    const int warp = tid >> 5;
    const int wm   = (warp & 1) * 64;
    const int wn   = (warp >> 1) * 32;
    const int gr   = lane >> 2;
    const int tq   = lane & 3;

    float acc[4][4][4] = {};

    auto loadTiles = [&](int stage, int k0) {
#pragma unroll
        for (int u = 0; u < 2; u++) {
            int c = tid * 2 + u;
            int r = c >> 2, kc = (c & 3) * 4;
            uint32_t dst = (uint32_t)__cvta_generic_to_shared(&As[stage][r * ASTR + kc]);
            const float* src = A + (size_t)(m0 + r) * K + k0 + kc;
            asm volatile("cp.async.cg.shared.global [%0], [%1], 16;\n" :: "r"(dst), "l"(src));
        }
#pragma unroll
        for (int u = 0; u < 2; u++) {
            int c = tid * 2 + u;
            int r = c >> 5, nc = (c & 31) * 4;
            uint32_t dst = (uint32_t)__cvta_generic_to_shared(&Bs[stage][r * BSTR + nc]);
            const float* src = B + (size_t)(k0 + r) * Nn + n0 + nc;
            asm volatile("cp.async.cg.shared.global [%0], [%1], 16;\n" :: "r"(dst), "l"(src));
        }
    };

    const int nit = K / BK;
    loadTiles(0, 0);
    asm volatile("cp.async.commit_group;\n" ::: "memory");

    for (int it = 0; it < nit; ++it) {
        if (it + 1 < nit) loadTiles((it + 1) & 1, (it + 1) * BK);
        asm volatile("cp.async.commit_group;\n" ::: "memory");
        asm volatile("cp.async.wait_group 1;\n" ::: "memory");
        __syncthreads();

        const float* as = As[it & 1];
        const float* bs = Bs[it & 1];

#pragma unroll
        for (int ks = 0; ks < 2; ++ks) {
            const int k = ks * 8;
            uint32_t af[4][4], bf[4][2];
#pragma unroll
            for (int im = 0; im < 4; im++) {
                const int mb = wm + im * 16;
                af[im][0] = f2tf32(as[(mb + gr)     * ASTR + k + tq]);
                af[im][1] = f2tf32(as[(mb + gr + 8) * ASTR + k + tq]);
                af[im][2] = f2tf32(as[(mb + gr)     * ASTR + k + tq + 4]);
                af[im][3] = f2tf32(as[(mb + gr + 8) * ASTR + k + tq + 4]);
            }
#pragma unroll
            for (int jn = 0; jn < 4; jn++) {
                const int nb = wn + jn * 8;
                bf[jn][0] = f2tf32(bs[(k + tq)     * BSTR + nb + gr]);
                bf[jn][1] = f2tf32(bs[(k + tq + 4) * BSTR + nb + gr]);
            }
#pragma unroll
            for (int im = 0; im < 4; im++)
#pragma unroll
                for (int jn = 0; jn < 4; jn++)
                    mma_tf32(acc[im][jn][0], acc[im][jn][1], acc[im][jn][2], acc[im][jn][3],
                             af[im][0], af[im][1], af[im][2], af[im][3],
                             bf[jn][0], bf[jn][1]);
        }
        __syncthreads();
    }

#pragma unroll
    for (int im = 0; im < 4; im++) {
        const int mrow = m0 + wm + im * 16 + gr;
#pragma unroll
        for (int jn = 0; jn < 4; jn++) {
            const int ncol = n0 + wn + jn * 8 + 2 * tq;
            const float b0v = bias[ncol], b1v = bias[ncol + 1];
            float2 o0 = make_float2(acc[im][jn][0] + b0v, acc[im][jn][1] + b1v);
            float2 o1 = make_float2(acc[im][jn][2] + b0v, acc[im][jn][3] + b1v);
            *(float2*)&C[(size_t)mrow       * Nn + ncol] = o0;
            *(float2*)&C[(size_t)(mrow + 8) * Nn + ncol] = o1;
        }
    }
}

// ---------------------------------------------------------------------------
// Fused windowed attention with inline RoPE+RMS+roll.
// One CTA per (window, head), 256 thr / 8 warps.
// Reads raw qkv rows at rolled token index (w*256+i+SHIFT) mod N; one warp
// per row: lane m owns RoPE pair (2m, 2m+1), sincosf per row, warp-reduce RMS.
// smem: K[256][68], V^T[64][260], S[64][260], Q[64][68], rowsum[64] (~220 KB)
// ---------------------------------------------------------------------------
constexpr int KSTR = 68;    // K,Q smem stride (conflict-free fragment reads)
constexpr int SSTR = 260;   // S,VT smem stride
constexpr int kAttnSmemFloats = kW * KSTR + kD * SSTR + 64 * SSTR + 64 * KSTR + 64;

__global__ void __launch_bounds__(256, 1) attn_tc_kernel(
    const float* __restrict__ qkv, const int* __restrict__ coords,
    const float* __restrict__ gamma_q, const float* __restrict__ gamma_k,
    float* __restrict__ gh)
{
    extern __shared__ float smem[];
    float* Ks = smem;                    // 256*68
    float* VT = Ks + kW * KSTR;          // 64*260 (V transposed: VT[d][kv])
    float* Ss = VT + kD * SSTR;          // 64*260
    float* Qs = Ss + 64 * SSTR;          // 64*68
    float* rs = Qs + 64 * KSTR;          // 64 row sums

    const int w   = blockIdx.x;
    const int h   = blockIdx.y;
    const int tid = threadIdx.x;
    const int lane = tid & 31;
    const int warp = tid >> 5;
    const int gr = lane >> 2;   // 0..7
    const int tq = lane & 3;    // 0..3

    // per-lane RoPE constants: pair m = lane. theta = coords[c]*freq, c=m/10,
    // freq = 10000^{-(m%10)/10}; pairs 30,31 have theta=0.
    const int  cidx  = (lane < 30) ? (lane / 10) : 0;
    const bool hasth = (lane < 30);
    const float freq = hasth ? __powf(10000.0f, -(float)(lane % 10) * 0.1f) : 0.0f;
    const float2 gk2 = *(const float2*)&gamma_k[h * kD + 2 * lane];
    const float2 gq2 = *(const float2*)&gamma_q[h * kD + 2 * lane];

    // ---- load K (rope+rms) and V^T; one warp per row, 32 rows per warp ----
    for (int r = warp * 32; r < warp * 32 + 32; r++) {
        const int token = (w * kW + r + kSHIFT) & (kN - 1);
        const float* base = qkv + (size_t)token * kC3 + h * kD + 2 * lane;

        float th = hasth ? (float)__ldg(&coords[token * 3 + cidx]) * freq : 0.0f;
        float c, s;
        sincosf(th, &s, &c);   // FIX: sincosf(x, sin*, cos*) — was swapped

        // K: rotate + RMS
        float2 kv = *(const float2*)&base[kC];
        float kr0 = kv.x * c - kv.y * s;
        float kr1 = kv.x * s + kv.y * c;
        float sq = kr0 * kr0 + kr1 * kr1;
#pragma unroll
        for (int off = 16; off > 0; off >>= 1)
            sq += __shfl_xor_sync(0xffffffffu, sq, off);
        float inv = 8.0f * rsqrtf(sq + 1e-12f);
        *(float2*)&Ks[r * KSTR + 2 * lane] =
            make_float2(kr0 * inv * gk2.x, kr1 * inv * gk2.y);

        // V: plain transpose copy
        float2 vv = *(const float2*)&base[2 * kC];
        VT[(2 * lane + 0) * SSTR + r] = vv.x;
        VT[(2 * lane + 1) * SSTR + r] = vv.y;
    }

    for (int qb = 0; qb < 4; qb++) {
        __syncthreads();
        // ---- load Q block (64 rows, 8 per warp) with rope+rms ----
        for (int rr = 0; rr < 8; rr++) {
            const int r = warp * 8 + rr;
            const int token = (w * kW + qb * 64 + r + kSHIFT) & (kN - 1);
            const float* base = qkv + (size_t)token * kC3 + h * kD + 2 * lane;

            float th = hasth ? (float)__ldg(&coords[token * 3 + cidx]) * freq : 0.0f;
            float c, s;
            sincosf(th, &s, &c);   // FIX: sincosf(x, sin*, cos*)

            float2 qv = *(const float2*)base;
            float qr0 = qv.x * c - qv.y * s;
            float qr1 = qv.x * s + qv.y * c;
            float sq = qr0 * qr0 + qr1 * qr1;
#pragma unroll
            for (int off = 16; off > 0; off >>= 1)
                sq += __shfl_xor_sync(0xffffffffu, sq, off);
            float inv = 8.0f * rsqrtf(sq + 1e-12f);
            *(float2*)&Qs[r * KSTR + 2 * lane] =
                make_float2(qr0 * inv * gq2.x, qr1 * inv * gq2.y);
        }
        __syncthreads();

        // ---- phase 1: S = Q K^T, warp owns n-slice [warp*32, warp*32+32) ----
        {
            const int wn = warp * 32;
            float acc[4][4][4] = {};
#pragma unroll
            for (int ks = 0; ks < 8; ks++) {
                const int k = ks * 8;
                uint32_t af[4][4], bf[4][2];
#pragma unroll
                for (int im = 0; im < 4; im++) {
                    const int mb = im * 16;
                    af[im][0] = f2tf32(Qs[(mb + gr)     * KSTR + k + tq]);
                    af[im][1] = f2tf32(Qs[(mb + gr + 8) * KSTR + k + tq]);
                    af[im][2] = f2tf32(Qs[(mb + gr)     * KSTR + k + tq + 4]);
                    af[im][3] = f2tf32(Qs[(mb + gr + 8) * KSTR + k + tq + 4]);
                }
#pragma unroll
                for (int jn = 0; jn < 4; jn++) {
                    const int nb = wn + jn * 8;
                    bf[jn][0] = f2tf32(Ks[(nb + gr) * KSTR + k + tq]);
                    bf[jn][1] = f2tf32(Ks[(nb + gr) * KSTR + k + tq + 4]);
                }
#pragma unroll
                for (int im = 0; im < 4; im++)
#pragma unroll
                    for (int jn = 0; jn < 4; jn++)
                        mma_tf32(acc[im][jn][0], acc[im][jn][1], acc[im][jn][2], acc[im][jn][3],
                                 af[im][0], af[im][1], af[im][2], af[im][3],
                                 bf[jn][0], bf[jn][1]);
            }
#pragma unroll
            for (int im = 0; im < 4; im++) {
                const int r0 = im * 16 + gr;
#pragma unroll
                for (int jn = 0; jn < 4; jn++) {
                    const int c = wn + jn * 8 + 2 * tq;
                    *(float2*)&Ss[r0 * SSTR + c] =
                        make_float2(acc[im][jn][0] * kSCALE, acc[im][jn][1] * kSCALE);
                    *(float2*)&Ss[(r0 + 8) * SSTR + c] =
                        make_float2(acc[im][jn][2] * kSCALE, acc[im][jn][3] * kSCALE);
                }
            }
        }
        __syncthreads();

        // ---- phase 2: softmax (warp handles rows warp*8..warp*8+7) ----
        for (int rr = 0; rr < 8; rr++) {
            const int r = warp * 8 + rr;
            float v[8];
            float m = -1e30f;
#pragma unroll
            for (int i = 0; i < 8; i++) {
                v[i] = Ss[r * SSTR + lane + 32 * i];
                m = fmaxf(m, v[i]);
            }
#pragma unroll
            for (int off = 16; off > 0; off >>= 1)
                m = fmaxf(m, __shfl_xor_sync(0xffffffffu, m, off));
            float sum = 0.0f;
#pragma unroll
            for (int i = 0; i < 8; i++) {
                v[i] = __expf(v[i] - m);
                sum += v[i];
                Ss[r * SSTR + lane + 32 * i] = v[i];
            }
#pragma unroll
            for (int off = 16; off > 0; off >>= 1)
                sum += __shfl_xor_sync(0xffffffffu, sum, off);
            if (lane == 0) rs[r] = sum;
        }
        __syncthreads();

        // ---- phase 3: O = P V  (M=64 N=64 K=256; warp tile 16x32) ----
        {
            const int wm  = (warp >> 1) * 16;
            const int wn2 = (warp & 1) * 32;
            float acc[4][4] = {};
#pragma unroll
            for (int ks = 0; ks < 32; ks++) {
                const int k = ks * 8;
                uint32_t af[4], bf[4][2];
                af[0] = f2tf32(Ss[(wm + gr)     * SSTR + k + tq]);
                af[1] = f2tf32(Ss[(wm + gr + 8) * SSTR + k + tq]);
                af[2] = f2tf32(Ss[(wm + gr)     * SSTR + k + tq + 4]);
                af[3] = f2tf32(Ss[(wm + gr + 8) * SSTR + k + tq + 4]);
#pragma unroll
                for (int jn = 0; jn < 4; jn++) {
                    const int nb = wn2 + jn * 8;
                    bf[jn][0] = f2tf32(VT[(nb + gr) * SSTR + k + tq]);
                    bf[jn][1] = f2tf32(VT[(nb + gr) * SSTR + k + tq + 4]);
                }
#pragma unroll
                for (int jn = 0; jn < 4; jn++)
                    mma_tf32(acc[jn][0], acc[jn][1], acc[jn][2], acc[jn][3],
                             af[0], af[1], af[2], af[3], bf[jn][0], bf[jn][1]);
            }
            // store O (rolled +SHIFT), scale by 1/rowsum
            const float inv0 = 1.0f / rs[wm + gr];
            const float inv1 = 1.0f / rs[wm + gr + 8];
            const int q0 = w * kW + qb * 64 + wm + gr;
            const size_t io0 = (size_t)((q0 + kSHIFT) & (kN - 1));
            const size_t io1 = (size_t)((q0 + 8 + kSHIFT) & (kN - 1));
#pragma unroll
            for (int jn = 0; jn < 4; jn++) {
                const int c = h * kD + wn2 + jn * 8 + 2 * tq;
                *(float2*)&gh[io0 * kC + c] =
                    make_float2(acc[jn][0] * inv0, acc[jn][1] * inv0);
                *(float2*)&gh[io1 * kC + c] =
                    make_float2(acc[jn][2] * inv1, acc[jn][3] * inv1);
            }
        }
    }
}

// ---------------------------------------------------------------------------
extern "C" void kernel_launch(void* const* d_in, const int* in_sizes, int n_in,
                              void* d_out, int out_size)
{
    const float* x      = (const float*)d_in[0];
    const int*   coords = (const int*)  d_in[1];
    const float* Wqkv   = (const float*)d_in[2];
    const float* b_qkv  = (const float*)d_in[3];
    const float* gamq   = (const float*)d_in[4];
    const float* gamk   = (const float*)d_in[5];
    const float* Wout   = (const float*)d_in[6];
    const float* b_out  = (const float*)d_in[7];
    float* out = (float*)d_out;

    float *pqkv, *ph;
    cudaGetSymbolAddress((void**)&pqkv, g_qkv);
    cudaGetSymbolAddress((void**)&ph,   g_h);

    // 1) qkv = x @ Wqkv + b_qkv   (tf32 tensor cores)
    gemm_tf32_bias<<<dim3(kC3 / 128, kN / 128), 256>>>(x, Wqkv, b_qkv, pqkv, kN, kC3, kC);

    // 2) fused RoPE+RMS+roll + windowed attention (tensor cores)
    static const int kAttnSmem = kAttnSmemFloats * (int)sizeof(float);  // ~220 KB
    cudaFuncSetAttribute(attn_tc_kernel, cudaFuncAttributeMaxDynamicSharedMemorySize, kAttnSmem);
    attn_tc_kernel<<<dim3(kNW, kH), 256, kAttnSmem>>>(pqkv, coords, gamq, gamk, ph);

    // 3) out = h @ Wout + b_out   (tf32 tensor cores)
    gemm_tf32_bias<<<dim3(kC / 128, kN / 128), 256>>>(ph, Wout, b_out, out, kN, kC, kC);
}

// round 11
// speedup vs baseline: 1.3273x; 1.3273x over previous
#include <cuda_runtime.h>
#include <math.h>
#include <stdint.h>

// Problem constants
constexpr int kN  = 32768;
constexpr int kC  = 512;
constexpr int kC3 = 1536;
constexpr int kH  = 8;
constexpr int kD  = 64;
constexpr int kW  = 256;
constexpr int kNW = kN / kW;   // 128 windows
constexpr int kSHIFT = 128;
constexpr float kSCALE = 0.125f;  // 1/sqrt(64)

// Scratch (static device arrays — no allocation at runtime)
__device__ float g_qkv[(size_t)kN * kC3];  // 192 MB
__device__ float g_h[(size_t)kN * kC];     // attention output, un-rolled frame

__device__ __forceinline__ uint32_t f2tf32(float x) {
    uint32_t r;
    asm("cvt.rna.tf32.f32 %0, %1;" : "=r"(r) : "f"(x));
    return r;
}

__device__ __forceinline__ void mma_tf32(
    float& c0, float& c1, float& c2, float& c3,
    uint32_t a0, uint32_t a1, uint32_t a2, uint32_t a3,
    uint32_t b0, uint32_t b1)
{
    asm volatile(
        "mma.sync.aligned.m16n8k8.row.col.f32.tf32.tf32.f32 "
        "{%0,%1,%2,%3}, {%4,%5,%6,%7}, {%8,%9}, {%0,%1,%2,%3};"
        : "+f"(c0), "+f"(c1), "+f"(c2), "+f"(c3)
        : "r"(a0), "r"(a1), "r"(a2), "r"(a3), "r"(b0), "r"(b1));
}

// ---------------------------------------------------------------------------
// tf32 tensor-core GEMM with bias: C[M,Nn] = A[M,K] @ B[K,Nn] + bias[Nn]
// (unchanged — validated)
// ---------------------------------------------------------------------------
__global__ void __launch_bounds__(256, 2) gemm_tf32_bias(
    const float* __restrict__ A, const float* __restrict__ B,
    const float* __restrict__ bias, float* __restrict__ C,
    int M, int Nn, int K)
{
    constexpr int BM = 128, BN = 128, BK = 16;
    constexpr int ASTR = BK + 4;
    constexpr int BSTR = BN + 8;

    __shared__ float As[2][BM * ASTR];
    __shared__ float Bs[2][BK * BSTR];

    const int tid  = threadIdx.x;
    const int m0   = blockIdx.y * BM;
    const int n0   = blockIdx.x * BN;
    const int lane = tid & 31;
    const int warp = tid >> 5;
    const int wm   = (warp & 1) * 64;
    const int wn   = (warp >> 1) * 32;
    const int gr   = lane >> 2;
    const int tq   = lane & 3;

    float acc[4][4][4] = {};

    auto loadTiles = [&](int stage, int k0) {
#pragma unroll
        for (int u = 0; u < 2; u++) {
            int c = tid * 2 + u;
            int r = c >> 2, kc = (c & 3) * 4;
            uint32_t dst = (uint32_t)__cvta_generic_to_shared(&As[stage][r * ASTR + kc]);
            const float* src = A + (size_t)(m0 + r) * K + k0 + kc;
            asm volatile("cp.async.cg.shared.global [%0], [%1], 16;\n" :: "r"(dst), "l"(src));
        }
#pragma unroll
        for (int u = 0; u < 2; u++) {
            int c = tid * 2 + u;
            int r = c >> 5, nc = (c & 31) * 4;
            uint32_t dst = (uint32_t)__cvta_generic_to_shared(&Bs[stage][r * BSTR + nc]);
            const float* src = B + (size_t)(k0 + r) * Nn + n0 + nc;
            asm volatile("cp.async.cg.shared.global [%0], [%1], 16;\n" :: "r"(dst), "l"(src));
        }
    };

    const int nit = K / BK;
    loadTiles(0, 0);
    asm volatile("cp.async.commit_group;\n" ::: "memory");

    for (int it = 0; it < nit; ++it) {
        if (it + 1 < nit) loadTiles((it + 1) & 1, (it + 1) * BK);
        asm volatile("cp.async.commit_group;\n" ::: "memory");
        asm volatile("cp.async.wait_group 1;\n" ::: "memory");
        __syncthreads();

        const float* as = As[it & 1];
        const float* bs = Bs[it & 1];

#pragma unroll
        for (int ks = 0; ks < 2; ++ks) {
            const int k = ks * 8;
            uint32_t af[4][4], bf[4][2];
#pragma unroll
            for (int im = 0; im < 4; im++) {
                const int mb = wm + im * 16;
                af[im][0] = f2tf32(as[(mb + gr)     * ASTR + k + tq]);
                af[im][1] = f2tf32(as[(mb + gr + 8) * ASTR + k + tq]);
                af[im][2] = f2tf32(as[(mb + gr)     * ASTR + k + tq + 4]);
                af[im][3] = f2tf32(as[(mb + gr + 8) * ASTR + k + tq + 4]);
            }
#pragma unroll
            for (int jn = 0; jn < 4; jn++) {
                const int nb = wn + jn * 8;
                bf[jn][0] = f2tf32(bs[(k + tq)     * BSTR + nb + gr]);
                bf[jn][1] = f2tf32(bs[(k + tq + 4) * BSTR + nb + gr]);
            }
#pragma unroll
            for (int im = 0; im < 4; im++)
#pragma unroll
                for (int jn = 0; jn < 4; jn++)
                    mma_tf32(acc[im][jn][0], acc[im][jn][1], acc[im][jn][2], acc[im][jn][3],
                             af[im][0], af[im][1], af[im][2], af[im][3],
                             bf[jn][0], bf[jn][1]);
        }
        __syncthreads();
    }

#pragma unroll
    for (int im = 0; im < 4; im++) {
        const int mrow = m0 + wm + im * 16 + gr;
#pragma unroll
        for (int jn = 0; jn < 4; jn++) {
            const int ncol = n0 + wn + jn * 8 + 2 * tq;
            const float b0v = bias[ncol], b1v = bias[ncol + 1];
            float2 o0 = make_float2(acc[im][jn][0] + b0v, acc[im][jn][1] + b1v);
            float2 o1 = make_float2(acc[im][jn][2] + b0v, acc[im][jn][3] + b1v);
            *(float2*)&C[(size_t)mrow       * Nn + ncol] = o0;
            *(float2*)&C[(size_t)(mrow + 8) * Nn + ncol] = o1;
        }
    }
}

// ---------------------------------------------------------------------------
// Fused windowed attention with inline RoPE+RMS+roll — latency-tolerant loads.
// One CTA per (window, head), 256 thr / 8 warps.
// Coords are prefetched per-lane at CTA start and distributed via shfl;
// gmem rows are loaded in groups of 4 (MLP=8) before any dependent math.
// ---------------------------------------------------------------------------
constexpr int KSTR = 68;    // K,Q smem stride (conflict-free fragment reads)
constexpr int SSTR = 260;   // S,VT smem stride
constexpr int kAttnSmemFloats = kW * KSTR + kD * SSTR + 64 * SSTR + 64 * KSTR + 64;

__global__ void __launch_bounds__(256, 1) attn_tc_kernel(
    const float* __restrict__ qkv, const int* __restrict__ coords,
    const float* __restrict__ gamma_q, const float* __restrict__ gamma_k,
    float* __restrict__ gh)
{
    extern __shared__ float smem[];
    float* Ks = smem;                    // 256*68
    float* VT = Ks + kW * KSTR;          // 64*260 (V transposed: VT[d][kv])
    float* Ss = VT + kD * SSTR;          // 64*260
    float* Qs = Ss + 64 * SSTR;          // 64*68
    float* rs = Qs + 64 * KSTR;          // 64 row sums

    const int w   = blockIdx.x;
    const int h   = blockIdx.y;
    const int tid = threadIdx.x;
    const int lane = tid & 31;
    const int warp = tid >> 5;
    const int gr = lane >> 2;   // 0..7
    const int tq = lane & 3;    // 0..3
    const unsigned FULL = 0xffffffffu;

    // per-lane RoPE constants: pair m = lane. theta = coords[c]*freq, c=m/10,
    // freq = 10000^{-(m%10)/10}; pairs 30,31 have theta=0.
    const int  cidx  = (lane < 30) ? (lane / 10) : 0;
    const bool hasth = (lane < 30);
    const float freq = hasth ? __powf(10000.0f, -(float)(lane % 10) * 0.1f) : 0.0f;
    const float2 gk2 = *(const float2*)&gamma_k[h * kD + 2 * lane];
    const float2 gq2 = *(const float2*)&gamma_q[h * kD + 2 * lane];

    // ---- prefetch coords (parallel LDGs, distributed later via shfl) ----
    // K side: lane holds coords for row warp*32+lane
    const int krow_l   = warp * 32 + lane;
    const int ktoken_l = (w * kW + krow_l + kSHIFT) & (kN - 1);
    const int kc0 = __ldg(&coords[ktoken_l * 3 + 0]);
    const int kc1 = __ldg(&coords[ktoken_l * 3 + 1]);
    const int kc2 = __ldg(&coords[ktoken_l * 3 + 2]);
    // Q side: lane holds coords for row (lane/8)*64 + warp*8 + (lane%8)
    const int qrow_l   = (lane >> 3) * 64 + warp * 8 + (lane & 7);
    const int qtoken_l = (w * kW + qrow_l + kSHIFT) & (kN - 1);
    const int qc0 = __ldg(&coords[qtoken_l * 3 + 0]);
    const int qc1 = __ldg(&coords[qtoken_l * 3 + 1]);
    const int qc2 = __ldg(&coords[qtoken_l * 3 + 2]);

    // ---- K (rope+rms) and V^T load: 8 groups of 4 rows, loads batched ----
    for (int g = 0; g < 8; g++) {
        float2 kd[4], vd[4];
#pragma unroll
        for (int u = 0; u < 4; u++) {
            const int r = warp * 32 + g * 4 + u;
            const int token = (w * kW + r + kSHIFT) & (kN - 1);
            const float* base = qkv + (size_t)token * kC3 + h * kD + 2 * lane;
            kd[u] = *(const float2*)&base[kC];
            vd[u] = *(const float2*)&base[2 * kC];
        }
#pragma unroll
        for (int u = 0; u < 4; u++) {
            const int r = warp * 32 + g * 4 + u;
            const int ridx = g * 4 + u;
            const float c0 = (float)__shfl_sync(FULL, kc0, ridx);
            const float c1 = (float)__shfl_sync(FULL, kc1, ridx);
            const float c2 = (float)__shfl_sync(FULL, kc2, ridx);
            const float coord = (cidx == 0) ? c0 : ((cidx == 1) ? c1 : c2);
            const float th = hasth ? coord * freq : 0.0f;
            float s, c;
            __sincosf(th, &s, &c);

            float kr0 = kd[u].x * c - kd[u].y * s;
            float kr1 = kd[u].x * s + kd[u].y * c;
            float sq = kr0 * kr0 + kr1 * kr1;
#pragma unroll
            for (int off = 16; off > 0; off >>= 1)
                sq += __shfl_xor_sync(FULL, sq, off);
            float inv = 8.0f * rsqrtf(sq + 1e-12f);
            *(float2*)&Ks[r * KSTR + 2 * lane] =
                make_float2(kr0 * inv * gk2.x, kr1 * inv * gk2.y);

            VT[(2 * lane + 0) * SSTR + r] = vd[u].x;
            VT[(2 * lane + 1) * SSTR + r] = vd[u].y;
        }
    }

    for (int qb = 0; qb < 4; qb++) {
        __syncthreads();
        // ---- Q block load (8 rows/warp) in 2 groups of 4, loads batched ----
        for (int g = 0; g < 2; g++) {
            float2 qd[4];
#pragma unroll
            for (int u = 0; u < 4; u++) {
                const int rl = warp * 8 + g * 4 + u;              // 0..63 local
                const int token = (w * kW + qb * 64 + rl + kSHIFT) & (kN - 1);
                const float* base = qkv + (size_t)token * kC3 + h * kD + 2 * lane;
                qd[u] = *(const float2*)base;
            }
#pragma unroll
            for (int u = 0; u < 4; u++) {
                const int rl = warp * 8 + g * 4 + u;
                const int ridx = qb * 8 + g * 4 + u;   // lane holding these coords
                const float c0 = (float)__shfl_sync(FULL, qc0, ridx);
                const float c1 = (float)__shfl_sync(FULL, qc1, ridx);
                const float c2 = (float)__shfl_sync(FULL, qc2, ridx);
                const float coord = (cidx == 0) ? c0 : ((cidx == 1) ? c1 : c2);
                const float th = hasth ? coord * freq : 0.0f;
                float s, c;
                __sincosf(th, &s, &c);

                float qr0 = qd[u].x * c - qd[u].y * s;
                float qr1 = qd[u].x * s + qd[u].y * c;
                float sq = qr0 * qr0 + qr1 * qr1;
#pragma unroll
                for (int off = 16; off > 0; off >>= 1)
                    sq += __shfl_xor_sync(FULL, sq, off);
                float inv = 8.0f * rsqrtf(sq + 1e-12f);
                *(float2*)&Qs[rl * KSTR + 2 * lane] =
                    make_float2(qr0 * inv * gq2.x, qr1 * inv * gq2.y);
            }
        }
        __syncthreads();

        // ---- phase 1: S = Q K^T, warp owns n-slice [warp*32, warp*32+32) ----
        {
            const int wn = warp * 32;
            float acc[4][4][4] = {};
#pragma unroll
            for (int ks = 0; ks < 8; ks++) {
                const int k = ks * 8;
                uint32_t af[4][4], bf[4][2];
#pragma unroll
                for (int im = 0; im < 4; im++) {
                    const int mb = im * 16;
                    af[im][0] = f2tf32(Qs[(mb + gr)     * KSTR + k + tq]);
                    af[im][1] = f2tf32(Qs[(mb + gr + 8) * KSTR + k + tq]);
                    af[im][2] = f2tf32(Qs[(mb + gr)     * KSTR + k + tq + 4]);
                    af[im][3] = f2tf32(Qs[(mb + gr + 8) * KSTR + k + tq + 4]);
                }
#pragma unroll
                for (int jn = 0; jn < 4; jn++) {
                    const int nb = wn + jn * 8;
                    bf[jn][0] = f2tf32(Ks[(nb + gr) * KSTR + k + tq]);
                    bf[jn][1] = f2tf32(Ks[(nb + gr) * KSTR + k + tq + 4]);
                }
#pragma unroll
                for (int im = 0; im < 4; im++)
#pragma unroll
                    for (int jn = 0; jn < 4; jn++)
                        mma_tf32(acc[im][jn][0], acc[im][jn][1], acc[im][jn][2], acc[im][jn][3],
                                 af[im][0], af[im][1], af[im][2], af[im][3],
                                 bf[jn][0], bf[jn][1]);
            }
#pragma unroll
            for (int im = 0; im < 4; im++) {
                const int r0 = im * 16 + gr;
#pragma unroll
                for (int jn = 0; jn < 4; jn++) {
                    const int c = wn + jn * 8 + 2 * tq;
                    *(float2*)&Ss[r0 * SSTR + c] =
                        make_float2(acc[im][jn][0] * kSCALE, acc[im][jn][1] * kSCALE);
                    *(float2*)&Ss[(r0 + 8) * SSTR + c] =
                        make_float2(acc[im][jn][2] * kSCALE, acc[im][jn][3] * kSCALE);
                }
            }
        }
        __syncthreads();

        // ---- phase 2: softmax (warp handles rows warp*8..warp*8+7) ----
        for (int rr = 0; rr < 8; rr++) {
            const int r = warp * 8 + rr;
            float v[8];
            float m = -1e30f;
#pragma unroll
            for (int i = 0; i < 8; i++) {
                v[i] = Ss[r * SSTR + lane + 32 * i];
                m = fmaxf(m, v[i]);
            }
#pragma unroll
            for (int off = 16; off > 0; off >>= 1)
                m = fmaxf(m, __shfl_xor_sync(FULL, m, off));
            float sum = 0.0f;
#pragma unroll
            for (int i = 0; i < 8; i++) {
                v[i] = __expf(v[i] - m);
                sum += v[i];
                Ss[r * SSTR + lane + 32 * i] = v[i];
            }
#pragma unroll
            for (int off = 16; off > 0; off >>= 1)
                sum += __shfl_xor_sync(FULL, sum, off);
            if (lane == 0) rs[r] = sum;
        }
        __syncthreads();

        // ---- phase 3: O = P V  (M=64 N=64 K=256; warp tile 16x32) ----
        {
            const int wm  = (warp >> 1) * 16;
            const int wn2 = (warp & 1) * 32;
            float acc[4][4] = {};
#pragma unroll
            for (int ks = 0; ks < 32; ks++) {
                const int k = ks * 8;
                uint32_t af[4], bf[4][2];
                af[0] = f2tf32(Ss[(wm + gr)     * SSTR + k + tq]);
                af[1] = f2tf32(Ss[(wm + gr + 8) * SSTR + k + tq]);
                af[2] = f2tf32(Ss[(wm + gr)     * SSTR + k + tq + 4]);
                af[3] = f2tf32(Ss[(wm + gr + 8) * SSTR + k + tq + 4]);
#pragma unroll
                for (int jn = 0; jn < 4; jn++) {
                    const int nb = wn2 + jn * 8;
                    bf[jn][0] = f2tf32(VT[(nb + gr) * SSTR + k + tq]);
                    bf[jn][1] = f2tf32(VT[(nb + gr) * SSTR + k + tq + 4]);
                }
#pragma unroll
                for (int jn = 0; jn < 4; jn++)
                    mma_tf32(acc[jn][0], acc[jn][1], acc[jn][2], acc[jn][3],
                             af[0], af[1], af[2], af[3], bf[jn][0], bf[jn][1]);
            }
            // store O (rolled +SHIFT), scale by 1/rowsum
            const float inv0 = 1.0f / rs[wm + gr];
            const float inv1 = 1.0f / rs[wm + gr + 8];
            const int q0 = w * kW + qb * 64 + wm + gr;
            const size_t io0 = (size_t)((q0 + kSHIFT) & (kN - 1));
            const size_t io1 = (size_t)((q0 + 8 + kSHIFT) & (kN - 1));
#pragma unroll
            for (int jn = 0; jn < 4; jn++) {
                const int c = h * kD + wn2 + jn * 8 + 2 * tq;
                *(float2*)&gh[io0 * kC + c] =
                    make_float2(acc[jn][0] * inv0, acc[jn][1] * inv0);
                *(float2*)&gh[io1 * kC + c] =
                    make_float2(acc[jn][2] * inv1, acc[jn][3] * inv1);
            }
        }
    }
}

// ---------------------------------------------------------------------------
extern "C" void kernel_launch(void* const* d_in, const int* in_sizes, int n_in,
                              void* d_out, int out_size)
{
    const float* x      = (const float*)d_in[0];
    const int*   coords = (const int*)  d_in[1];
    const float* Wqkv   = (const float*)d_in[2];
    const float* b_qkv  = (const float*)d_in[3];
    const float* gamq   = (const float*)d_in[4];
    const float* gamk   = (const float*)d_in[5];
    const float* Wout   = (const float*)d_in[6];
    const float* b_out  = (const float*)d_in[7];
    float* out = (float*)d_out;

    float *pqkv, *ph;
    cudaGetSymbolAddress((void**)&pqkv, g_qkv);
    cudaGetSymbolAddress((void**)&ph,   g_h);

    // 1) qkv = x @ Wqkv + b_qkv   (tf32 tensor cores)
    gemm_tf32_bias<<<dim3(kC3 / 128, kN / 128), 256>>>(x, Wqkv, b_qkv, pqkv, kN, kC3, kC);

    // 2) fused RoPE+RMS+roll + windowed attention (tensor cores)
    static const int kAttnSmem = kAttnSmemFloats * (int)sizeof(float);  // ~220 KB
    cudaFuncSetAttribute(attn_tc_kernel, cudaFuncAttributeMaxDynamicSharedMemorySize, kAttnSmem);
    attn_tc_kernel<<<dim3(kNW, kH), 256, kAttnSmem>>>(pqkv, coords, gamq, gamk, ph);

    // 3) out = h @ Wout + b_out   (tf32 tensor cores)
    gemm_tf32_bias<<<dim3(kC / 128, kN / 128), 256>>>(ph, Wout, b_out, out, kN, kC, kC);
}